// round 12
// baseline (speedup 1.0000x reference)
#include <cuda_runtime.h>
#include <cuda_fp16.h>
#include <cstdint>

#define NN 4096
#define DD 768
#define CADD (768.0f * 1e-6f * 1e-6f)

#define BK 64              // fp16 elements per K-chunk (128 bytes)
#define NKT 12             // 768 / 64
#define STAGE_A 16384      // 128 rows x 128B
#define STAGE_B 32768      // 256 rows x 128B
#define STAGE_BYTES (STAGE_A + STAGE_B)      // 49152
#define DYN_BYTES (2 * STAGE_BYTES)          // 98304 -> 2 CTAs/SM

// ---- scratch ----
__device__ __half g_A[(size_t)NN * DD];
__device__ __half g_B[(size_t)NN * DD];
__device__ float g_pa[NN];   // ||a||^2 + 2 eps sum(a) + d*eps^2
__device__ float g_pb[NN];   // ||b||^2 - 2 eps sum(b)
__device__ float g_part[512];
__device__ unsigned g_cnt;

// ============================================================
// helpers
// ============================================================
__device__ __forceinline__ uint32_t s2u(const void* p) {
    uint32_t a;
    asm("{ .reg .u64 t; cvta.to.shared.u64 t, %1; cvt.u32.u64 %0, t; }" : "=r"(a) : "l"(p));
    return a;
}
__device__ __forceinline__ void cp16(uint32_t s, const void* g) {
    asm volatile("cp.async.cg.shared.global [%0], [%1], 16;\n" :: "r"(s), "l"(g));
}
__device__ __forceinline__ uint32_t swz(uint32_t x) { return x ^ ((x >> 3) & 0x70); }

__device__ __forceinline__ void ldm4(unsigned& r0, unsigned& r1, unsigned& r2, unsigned& r3,
                                     uint32_t addr) {
    asm volatile("ldmatrix.sync.aligned.m8n8.x4.shared.b16 {%0,%1,%2,%3}, [%4];"
                 : "=r"(r0), "=r"(r1), "=r"(r2), "=r"(r3) : "r"(addr));
}
// fp16 MMA with fp16 accumulator: 2 accum regs per 16x8 tile
__device__ __forceinline__ void mma_h(unsigned* c, const unsigned* a, const unsigned* b) {
    asm volatile(
        "mma.sync.aligned.m16n8k16.row.col.f16.f16.f16.f16 "
        "{%0,%1}, {%2,%3,%4,%5}, {%6,%7}, {%0,%1};"
        : "+r"(c[0]), "+r"(c[1])
        : "r"(a[0]), "r"(a[1]), "r"(a[2]), "r"(a[3]), "r"(b[0]), "r"(b[1]));
}

// ============================================================
// Kernel 1: convert fp32 -> fp16 + row precompute + counter reset
// ============================================================
__global__ __launch_bounds__(256) void prep_kernel(const float* __restrict__ img,
                                                   const float* __restrict__ txt) {
    const int bid = blockIdx.x;
    const int which = bid >> 12;
    const int row = bid & 4095;
    const int t = threadIdx.x;
    if (bid == 0 && t == 0) g_cnt = 0;

    const float* r = (which ? txt : img) + (size_t)row * DD;
    __half* dst = (which ? g_B : g_A) + (size_t)row * DD;

    float s1 = 0.f, s2 = 0.f;
#pragma unroll
    for (int k = 0; k < 3; k++) {
        int idx = t + k * 256;
        float v = r[idx];
        s1 += v; s2 += v * v;
        dst[idx] = __float2half(v);
    }
#pragma unroll
    for (int o = 16; o; o >>= 1) {
        s1 += __shfl_xor_sync(0xffffffffu, s1, o);
        s2 += __shfl_xor_sync(0xffffffffu, s2, o);
    }
    __shared__ float sh1[8], sh2[8];
    if ((t & 31) == 0) { sh1[t >> 5] = s1; sh2[t >> 5] = s2; }
    __syncthreads();
    if (t == 0) {
        float a = 0.f, b = 0.f;
#pragma unroll
        for (int i = 0; i < 8; i++) { a += sh1[i]; b += sh2[i]; }
        if (which) g_pb[row] = b - 2.0f * 1e-6f * a;
        else       g_pa[row] = b + 2.0f * 1e-6f * a + CADD;
    }
}

// ============================================================
// Kernel 2: fp16 GEMM 128x256 (fp16 accum), warp tile 64x64,
// 8 warps (2x4), 2-stage cp.async + fused loss. grid (16,32).
// ============================================================
__device__ __forceinline__ void load_tile(int kt, int buf, int tid, int by, int bx, uint32_t sb) {
    const __half* gA = g_A + (size_t)by * 128 * DD + kt * BK;
    const __half* gB = g_B + (size_t)bx * 256 * DD + kt * BK;
    const uint32_t stA = sb + buf * STAGE_BYTES;
    const uint32_t stB = stA + STAGE_A;
#pragma unroll
    for (int h = 0; h < 4; h++) {                    // A: 128 rows x 8 chunks
        int id = tid + h * 256;
        int row = id >> 3, c = id & 7;
        cp16(stA + swz(row * 128 + c * 16), gA + (size_t)row * DD + c * 8);
    }
#pragma unroll
    for (int h = 0; h < 8; h++) {                    // B: 256 rows x 8 chunks
        int id = tid + h * 256;
        int row = id >> 3, c = id & 7;
        cp16(stB + swz(row * 128 + c * 16), gB + (size_t)row * DD + c * 8);
    }
}

__global__ __launch_bounds__(256, 2) void gemm_loss_kernel(const int* __restrict__ gt,
                                                           float* __restrict__ out) {
    extern __shared__ __align__(1024) char smem[];
    const uint32_t sb = s2u(smem);

    const int tid = threadIdx.x;
    const int lane = tid & 31, warp = tid >> 5;
    const int wm = warp >> 2;   // 0..1 -> 64 rows
    const int wn = warp & 3;    // 0..3 -> 64 cols
    const int bx = blockIdx.x, by = blockIdx.y;
    const int r16 = lane & 15, q = lane >> 4;

    unsigned c[4][8][2];
#pragma unroll
    for (int mi = 0; mi < 4; mi++)
#pragma unroll
        for (int ni = 0; ni < 8; ni++) { c[mi][ni][0] = 0u; c[mi][ni][1] = 0u; }

    // hoisted swizzled ldmatrix offsets; ks (32B) folds in via XOR
    const uint32_t qx = (q * 16) ^ ((r16 & 7) << 4);
    uint32_t aoff[4], boff[4];
#pragma unroll
    for (int mi = 0; mi < 4; mi++) aoff[mi] = (wm * 64 + mi * 16 + r16) * 128 + qx;
#pragma unroll
    for (int nh = 0; nh < 4; nh++) boff[nh] = STAGE_A + (wn * 64 + nh * 16 + r16) * 128 + qx;

    // prologue: stage 0
    load_tile(0, 0, tid, by, bx, sb);
    asm volatile("cp.async.commit_group;\n" ::: "memory");

    for (int kt = 0; kt < NKT; kt++) {
        asm volatile("cp.async.wait_group 0;\n" ::: "memory");
        __syncthreads();
        if (kt + 1 < NKT) load_tile(kt + 1, (kt + 1) & 1, tid, by, bx, sb);
        asm volatile("cp.async.commit_group;\n" ::: "memory");

        const uint32_t base = sb + (kt & 1) * STAGE_BYTES;
#pragma unroll
        for (int ks = 0; ks < 4; ks++) {
            const uint32_t kx = ks << 5;
            unsigned a[4][4];
#pragma unroll
            for (int mi = 0; mi < 4; mi++)
                ldm4(a[mi][0], a[mi][1], a[mi][2], a[mi][3], (base + aoff[mi]) ^ kx);
            unsigned b[8][2];
#pragma unroll
            for (int nh = 0; nh < 4; nh++) {
                unsigned t0, t1, t2, t3;
                ldm4(t0, t1, t2, t3, (base + boff[nh]) ^ kx);
                b[2 * nh][0] = t0;     b[2 * nh][1] = t2;
                b[2 * nh + 1][0] = t1; b[2 * nh + 1][1] = t3;
            }
#pragma unroll
            for (int mi = 0; mi < 4; mi++)
#pragma unroll
                for (int ni = 0; ni < 8; ni++)
                    mma_h(c[mi][ni], a[mi], b[ni]);
        }
    }

    // ---- fused loss epilogue (gt direct from gmem) ----
    float acc = 0.f;
#pragma unroll
    for (int mi = 0; mi < 4; mi++) {
        const int i0 = by * 128 + wm * 64 + mi * 16 + (lane >> 2);
        const float pa0 = g_pa[i0], pa1 = g_pa[i0 + 8];
#pragma unroll
        for (int ni = 0; ni < 8; ni++) {
            const int j0 = bx * 256 + wn * 64 + ni * 8 + (lane & 3) * 2;
            const float pb0 = g_pb[j0], pb1 = g_pb[j0 + 1];
            const int2 l0 = *reinterpret_cast<const int2*>(gt + (size_t)i0 * NN + j0);
            const int2 l1 = *reinterpret_cast<const int2*>(gt + (size_t)(i0 + 8) * NN + j0);
            const float2 f0 = __half22float2(*reinterpret_cast<const __half2*>(&c[mi][ni][0]));
            const float2 f1 = __half22float2(*reinterpret_cast<const __half2*>(&c[mi][ni][1]));
            {
                float d2 = fmaxf(fmaf(f0.x, -2.0f, pa0 + pb0), 0.0f);
                if (l0.x) { if (d2 < 4.0f) { float h = 2.0f - sqrtf(d2); acc += h * h; } }
                else acc += d2;
            }
            {
                float d2 = fmaxf(fmaf(f0.y, -2.0f, pa0 + pb1), 0.0f);
                if (l0.y) { if (d2 < 4.0f) { float h = 2.0f - sqrtf(d2); acc += h * h; } }
                else acc += d2;
            }
            {
                float d2 = fmaxf(fmaf(f1.x, -2.0f, pa1 + pb0), 0.0f);
                if (l1.x) { if (d2 < 4.0f) { float h = 2.0f - sqrtf(d2); acc += h * h; } }
                else acc += d2;
            }
            {
                float d2 = fmaxf(fmaf(f1.y, -2.0f, pa1 + pb1), 0.0f);
                if (l1.y) { if (d2 < 4.0f) { float h = 2.0f - sqrtf(d2); acc += h * h; } }
                else acc += d2;
            }
        }
    }

#pragma unroll
    for (int o = 16; o; o >>= 1) acc += __shfl_xor_sync(0xffffffffu, acc, o);
    __shared__ float red[8];
    __shared__ unsigned s_last;
    if (lane == 0) red[warp] = acc;
    __syncthreads();
    if (tid == 0) {
        float s = 0.f;
#pragma unroll
        for (int i = 0; i < 8; i++) s += red[i];
        g_part[by * 16 + bx] = s;
        __threadfence();
        s_last = (atomicAdd(&g_cnt, 1u) == 511u);
    }
    __syncthreads();

    if (s_last) {
        __threadfence();
        float s = g_part[tid] + g_part[tid + 256];
#pragma unroll
        for (int o = 16; o; o >>= 1) s += __shfl_xor_sync(0xffffffffu, s, o);
        if (lane == 0) red[warp] = s;
        __syncthreads();
        if (tid == 0) {
            float tot = 0.f;
#pragma unroll
            for (int i = 0; i < 8; i++) tot += red[i];
            out[0] = tot * (1.0f / 16777216.0f);
        }
    }
}

extern "C" void kernel_launch(void* const* d_in, const int* in_sizes, int n_in,
                              void* d_out, int out_size) {
    const float* img = (const float*)d_in[0];
    const float* txt = (const float*)d_in[1];
    const int* gt = (const int*)d_in[2];
    (void)in_sizes; (void)n_in; (void)out_size;

    cudaFuncSetAttribute(gemm_loss_kernel, cudaFuncAttributeMaxDynamicSharedMemorySize, DYN_BYTES);

    prep_kernel<<<8192, 256>>>(img, txt);
    dim3 grid(16, 32);
    gemm_loss_kernel<<<grid, 256, DYN_BYTES>>>(gt, (float*)d_out);
}

// round 13
// speedup vs baseline: 1.2218x; 1.2218x over previous
#include <cuda_runtime.h>
#include <cuda_fp16.h>
#include <cstdint>

#define NN 4096
#define DD 768
#define CADD (768.0f * 1e-6f * 1e-6f)

#define BK 64             // fp16 elements per K-chunk (128 bytes)
#define NKT 12            // 768 / 64
#define STAGE_BYTES 32768 // A 16KB + B 16KB
#define DYN_BYTES (2 * STAGE_BYTES)   // 64KB -> 3 CTAs/SM

// ---- scratch ----
__device__ __half g_A[(size_t)NN * DD];
__device__ __half g_B[(size_t)NN * DD];
__device__ float g_pa[NN];   // ||a||^2 + 2 eps sum(a) + d*eps^2
__device__ float g_pb[NN];   // ||b||^2 - 2 eps sum(b)
__device__ float g_part[1024];
__device__ unsigned g_cnt;

// ============================================================
// helpers
// ============================================================
__device__ __forceinline__ uint32_t s2u(const void* p) {
    uint32_t a;
    asm("{ .reg .u64 t; cvta.to.shared.u64 t, %1; cvt.u32.u64 %0, t; }" : "=r"(a) : "l"(p));
    return a;
}
__device__ __forceinline__ void cp16(uint32_t s, const void* g) {
    asm volatile("cp.async.cg.shared.global [%0], [%1], 16;\n" :: "r"(s), "l"(g));
}
__device__ __forceinline__ uint32_t swz(uint32_t x) { return x ^ ((x >> 3) & 0x70); }

__device__ __forceinline__ void ldm4(unsigned& r0, unsigned& r1, unsigned& r2, unsigned& r3,
                                     uint32_t addr) {
    asm volatile("ldmatrix.sync.aligned.m8n8.x4.shared.b16 {%0,%1,%2,%3}, [%4];"
                 : "=r"(r0), "=r"(r1), "=r"(r2), "=r"(r3) : "r"(addr));
}
// fp16 MMA with fp16 accumulator
__device__ __forceinline__ void mma_h(unsigned* c, const unsigned* a, const unsigned* b) {
    asm volatile(
        "mma.sync.aligned.m16n8k16.row.col.f16.f16.f16.f16 "
        "{%0,%1}, {%2,%3,%4,%5}, {%6,%7}, {%0,%1};"
        : "+r"(c[0]), "+r"(c[1])
        : "r"(a[0]), "r"(a[1]), "r"(a[2]), "r"(a[3]), "r"(b[0]), "r"(b[1]));
}

// ============================================================
// Kernel 1: convert fp32 -> fp16 + row precompute + counter reset
// ============================================================
__global__ __launch_bounds__(256) void prep_kernel(const float* __restrict__ img,
                                                   const float* __restrict__ txt) {
    const int bid = blockIdx.x;
    const int which = bid >> 12;
    const int row = bid & 4095;
    const int t = threadIdx.x;
    if (bid == 0 && t == 0) g_cnt = 0;

    const float* r = (which ? txt : img) + (size_t)row * DD;
    __half* dst = (which ? g_B : g_A) + (size_t)row * DD;

    float s1 = 0.f, s2 = 0.f;
#pragma unroll
    for (int k = 0; k < 3; k++) {
        int idx = t + k * 256;
        float v = r[idx];
        s1 += v; s2 += v * v;
        dst[idx] = __float2half(v);
    }
#pragma unroll
    for (int o = 16; o; o >>= 1) {
        s1 += __shfl_xor_sync(0xffffffffu, s1, o);
        s2 += __shfl_xor_sync(0xffffffffu, s2, o);
    }
    __shared__ float sh1[8], sh2[8];
    if ((t & 31) == 0) { sh1[t >> 5] = s1; sh2[t >> 5] = s2; }
    __syncthreads();
    if (t == 0) {
        float a = 0.f, b = 0.f;
#pragma unroll
        for (int i = 0; i < 8; i++) { a += sh1[i]; b += sh2[i]; }
        if (which) g_pb[row] = b - 2.0f * 1e-6f * a;
        else       g_pa[row] = b + 2.0f * 1e-6f * a + CADD;
    }
}

// ============================================================
// Kernel 2: fp16 GEMM 128x128 (fp16 accum), warp tile 64x32,
// 8 warps, 2-stage cp.async, 3 CTAs/SM, strength-reduced
// addressing + fused loss. grid (32,32).
// ============================================================
__global__ __launch_bounds__(256, 3) void gemm_loss_kernel(const int* __restrict__ gt,
                                                           float* __restrict__ out) {
    extern __shared__ __align__(1024) char smem[];
    const uint32_t sb = s2u(smem);

    const int tid = threadIdx.x;
    const int lane = tid & 31, warp = tid >> 5;
    const int wm = warp >> 2;   // 0..1 -> 64 rows
    const int wn = warp & 3;    // 0..3 -> 32 cols
    const int bx = blockIdx.x, by = blockIdx.y;
    const int r16 = lane & 15, q = lane >> 4;

    unsigned c[4][4][2];
#pragma unroll
    for (int mi = 0; mi < 4; mi++)
#pragma unroll
        for (int ni = 0; ni < 4; ni++) { c[mi][ni][0] = 0u; c[mi][ni][1] = 0u; }

    // ---- strength-reduced loader bases (affine in h: row step 32 keeps
    // row&7 fixed, so swizzle offset is h-invariant up to +4096h) ----
    const int lrow = tid >> 3, lcol = tid & 7;                 // 0..31, 0..7
    const uint32_t smA = sb + swz(lrow * 128 + lcol * 16);     // + buf*STAGE + h*4096
    const __half* gA0 = g_A + (size_t)by * 128 * DD + lrow * DD + lcol * 8;
    const __half* gB0 = g_B + (size_t)bx * 128 * DD + lrow * DD + lcol * 8;

    // hoisted swizzled ldmatrix offsets; ks (32B) folds in via XOR
    const uint32_t qx = (q * 16) ^ ((r16 & 7) << 4);
    uint32_t aoff[4], boff[2];
#pragma unroll
    for (int mi = 0; mi < 4; mi++) aoff[mi] = (wm * 64 + mi * 16 + r16) * 128 + qx;
#pragma unroll
    for (int nh = 0; nh < 2; nh++) boff[nh] = 16384 + (wn * 32 + nh * 16 + r16) * 128 + qx;

    // prologue: stage 0 (all addresses reg+immediate)
#pragma unroll
    for (int h = 0; h < 4; h++) {
        cp16(smA + h * 4096,         gA0 + h * 32 * DD);
        cp16(smA + 16384 + h * 4096, gB0 + h * 32 * DD);
    }
    asm volatile("cp.async.commit_group;\n" ::: "memory");

    for (int kt = 0; kt < NKT; kt++) {
        asm volatile("cp.async.wait_group 0;\n" ::: "memory");
        __syncthreads();
        if (kt + 1 < NKT) {
            const __half* ga = gA0 + (kt + 1) * BK;
            const __half* gb = gB0 + (kt + 1) * BK;
            const uint32_t sa = smA + ((kt + 1) & 1) * STAGE_BYTES;
#pragma unroll
            for (int h = 0; h < 4; h++) {
                cp16(sa + h * 4096,         ga + h * 32 * DD);
                cp16(sa + 16384 + h * 4096, gb + h * 32 * DD);
            }
        }
        asm volatile("cp.async.commit_group;\n" ::: "memory");

        const uint32_t base = sb + (kt & 1) * STAGE_BYTES;
#pragma unroll
        for (int ks = 0; ks < 4; ks++) {
            const uint32_t kx = ks << 5;
            unsigned a[4][4];
#pragma unroll
            for (int mi = 0; mi < 4; mi++)
                ldm4(a[mi][0], a[mi][1], a[mi][2], a[mi][3], (base + aoff[mi]) ^ kx);
            unsigned b[4][2];
#pragma unroll
            for (int nh = 0; nh < 2; nh++) {
                unsigned t0, t1, t2, t3;
                ldm4(t0, t1, t2, t3, (base + boff[nh]) ^ kx);
                b[2 * nh][0] = t0;     b[2 * nh][1] = t2;
                b[2 * nh + 1][0] = t1; b[2 * nh + 1][1] = t3;
            }
#pragma unroll
            for (int mi = 0; mi < 4; mi++)
#pragma unroll
                for (int ni = 0; ni < 4; ni++)
                    mma_h(c[mi][ni], a[mi], b[ni]);
        }
    }

    // ---- fused loss epilogue (gt direct from gmem; hidden by other CTAs) ----
    float acc = 0.f;
#pragma unroll
    for (int mi = 0; mi < 4; mi++) {
        const int i0 = by * 128 + wm * 64 + mi * 16 + (lane >> 2);
        const float pa0 = g_pa[i0], pa1 = g_pa[i0 + 8];
#pragma unroll
        for (int ni = 0; ni < 4; ni++) {
            const int j0 = bx * 128 + wn * 32 + ni * 8 + (lane & 3) * 2;
            const float pb0 = g_pb[j0], pb1 = g_pb[j0 + 1];
            const int2 l0 = *reinterpret_cast<const int2*>(gt + (size_t)i0 * NN + j0);
            const int2 l1 = *reinterpret_cast<const int2*>(gt + (size_t)(i0 + 8) * NN + j0);
            const float2 f0 = __half22float2(*reinterpret_cast<const __half2*>(&c[mi][ni][0]));
            const float2 f1 = __half22float2(*reinterpret_cast<const __half2*>(&c[mi][ni][1]));
            {
                float d2 = fmaxf(fmaf(f0.x, -2.0f, pa0 + pb0), 0.0f);
                if (l0.x) { if (d2 < 4.0f) { float h = 2.0f - sqrtf(d2); acc += h * h; } }
                else acc += d2;
            }
            {
                float d2 = fmaxf(fmaf(f0.y, -2.0f, pa0 + pb1), 0.0f);
                if (l0.y) { if (d2 < 4.0f) { float h = 2.0f - sqrtf(d2); acc += h * h; } }
                else acc += d2;
            }
            {
                float d2 = fmaxf(fmaf(f1.x, -2.0f, pa1 + pb0), 0.0f);
                if (l1.x) { if (d2 < 4.0f) { float h = 2.0f - sqrtf(d2); acc += h * h; } }
                else acc += d2;
            }
            {
                float d2 = fmaxf(fmaf(f1.y, -2.0f, pa1 + pb1), 0.0f);
                if (l1.y) { if (d2 < 4.0f) { float h = 2.0f - sqrtf(d2); acc += h * h; } }
                else acc += d2;
            }
        }
    }

#pragma unroll
    for (int o = 16; o; o >>= 1) acc += __shfl_xor_sync(0xffffffffu, acc, o);
    __shared__ float red[8];
    __shared__ unsigned s_last;
    if (lane == 0) red[warp] = acc;
    __syncthreads();
    if (tid == 0) {
        float s = 0.f;
#pragma unroll
        for (int i = 0; i < 8; i++) s += red[i];
        g_part[by * 32 + bx] = s;
        __threadfence();
        s_last = (atomicAdd(&g_cnt, 1u) == 1023u);
    }
    __syncthreads();

    if (s_last) {
        __threadfence();
        float s = g_part[tid] + g_part[tid + 256] + g_part[tid + 512] + g_part[tid + 768];
#pragma unroll
        for (int o = 16; o; o >>= 1) s += __shfl_xor_sync(0xffffffffu, s, o);
        if (lane == 0) red[warp] = s;
        __syncthreads();
        if (tid == 0) {
            float tot = 0.f;
#pragma unroll
            for (int i = 0; i < 8; i++) tot += red[i];
            out[0] = tot * (1.0f / 16777216.0f);
        }
    }
}

extern "C" void kernel_launch(void* const* d_in, const int* in_sizes, int n_in,
                              void* d_out, int out_size) {
    const float* img = (const float*)d_in[0];
    const float* txt = (const float*)d_in[1];
    const int* gt = (const int*)d_in[2];
    (void)in_sizes; (void)n_in; (void)out_size;

    cudaFuncSetAttribute(gemm_loss_kernel, cudaFuncAttributeMaxDynamicSharedMemorySize, DYN_BYTES);

    prep_kernel<<<8192, 256>>>(img, txt);
    dim3 grid(32, 32);
    gemm_loss_kernel<<<grid, 256, DYN_BYTES>>>(gt, (float*)d_out);
}

// round 14
// speedup vs baseline: 1.2859x; 1.0524x over previous
#include <cuda_runtime.h>
#include <cuda_fp16.h>
#include <cstdint>

#define NN 4096
#define DD 768
#define CADD (768.0f * 1e-6f * 1e-6f)

#define BK 64             // fp16 elements per K-chunk (128 bytes)
#define NKT 12            // 768 / 64
#define STAGE_BYTES 32768 // A 16KB + B 16KB
#define DYN_BYTES (2 * STAGE_BYTES)   // 64KB -> 3 CTAs/SM

// ---- scratch ----
__device__ __half g_A[(size_t)NN * DD];
__device__ __half g_B[(size_t)NN * DD];
__device__ float g_pa[NN];   // ||a||^2 + 2 eps sum(a) + d*eps^2
__device__ float g_pb[NN];   // ||b||^2 - 2 eps sum(b)
__device__ float g_part[1024];
__device__ unsigned g_cnt;

// ============================================================
// helpers
// ============================================================
__device__ __forceinline__ uint32_t s2u(const void* p) {
    uint32_t a;
    asm("{ .reg .u64 t; cvta.to.shared.u64 t, %1; cvt.u32.u64 %0, t; }" : "=r"(a) : "l"(p));
    return a;
}
__device__ __forceinline__ void cp16(uint32_t s, const void* g) {
    asm volatile("cp.async.cg.shared.global [%0], [%1], 16;\n" :: "r"(s), "l"(g));
}
__device__ __forceinline__ uint32_t swz(uint32_t x) { return x ^ ((x >> 3) & 0x70); }

__device__ __forceinline__ void ldm4(unsigned& r0, unsigned& r1, unsigned& r2, unsigned& r3,
                                     uint32_t addr) {
    asm volatile("ldmatrix.sync.aligned.m8n8.x4.shared.b16 {%0,%1,%2,%3}, [%4];"
                 : "=r"(r0), "=r"(r1), "=r"(r2), "=r"(r3) : "r"(addr));
}
// fp16 MMA with fp16 accumulator
__device__ __forceinline__ void mma_h(unsigned* c, const unsigned* a, const unsigned* b) {
    asm volatile(
        "mma.sync.aligned.m16n8k16.row.col.f16.f16.f16.f16 "
        "{%0,%1}, {%2,%3,%4,%5}, {%6,%7}, {%0,%1};"
        : "+r"(c[0]), "+r"(c[1])
        : "r"(a[0]), "r"(a[1]), "r"(a[2]), "r"(a[3]), "r"(b[0]), "r"(b[1]));
}

// ============================================================
// Kernel 1: warp-per-row convert + precompute (no smem, no barriers)
// 1024 blocks x 8 warps = 8192 warps; warp w -> row (w&4095) of A or B
// ============================================================
__global__ __launch_bounds__(256) void prep_kernel(const float* __restrict__ img,
                                                   const float* __restrict__ txt) {
    const int gw = blockIdx.x * 8 + (threadIdx.x >> 5);  // 0..8191
    const int lane = threadIdx.x & 31;
    const int which = gw >> 12;
    const int row = gw & 4095;
    if (gw == 0 && lane == 0) g_cnt = 0;

    const float4* src = reinterpret_cast<const float4*>(
        (which ? txt : img) + (size_t)row * DD);
    uint2* dst = reinterpret_cast<uint2*>((which ? g_B : g_A) + (size_t)row * DD);

    float s1 = 0.f, s2 = 0.f;
#pragma unroll
    for (int j = 0; j < 6; j++) {
        const int idx = lane + j * 32;      // 192 float4 per row
        float4 v = src[idx];
        s1 += (v.x + v.y) + (v.z + v.w);
        s2 += v.x * v.x + v.y * v.y + v.z * v.z + v.w * v.w;
        __half2 h0 = __floats2half2_rn(v.x, v.y);
        __half2 h1 = __floats2half2_rn(v.z, v.w);
        uint2 o;
        o.x = *reinterpret_cast<uint32_t*>(&h0);
        o.y = *reinterpret_cast<uint32_t*>(&h1);
        dst[idx] = o;
    }
#pragma unroll
    for (int o = 16; o; o >>= 1) {
        s1 += __shfl_xor_sync(0xffffffffu, s1, o);
        s2 += __shfl_xor_sync(0xffffffffu, s2, o);
    }
    if (lane == 0) {
        if (which) g_pb[row] = s2 - 2.0f * 1e-6f * s1;
        else       g_pa[row] = s2 + 2.0f * 1e-6f * s1 + CADD;
    }
}

// ============================================================
// Kernel 2: fp16 GEMM 128x128 (fp16 accum), warp tile 64x32,
// 8 warps, 2-stage cp.async, 3 CTAs/SM, strength-reduced
// addressing + fused loss. grid (32,32).  [R13 champion, unchanged]
// ============================================================
__global__ __launch_bounds__(256, 3) void gemm_loss_kernel(const int* __restrict__ gt,
                                                           float* __restrict__ out) {
    extern __shared__ __align__(1024) char smem[];
    const uint32_t sb = s2u(smem);

    const int tid = threadIdx.x;
    const int lane = tid & 31, warp = tid >> 5;
    const int wm = warp >> 2;   // 0..1 -> 64 rows
    const int wn = warp & 3;    // 0..3 -> 32 cols
    const int bx = blockIdx.x, by = blockIdx.y;
    const int r16 = lane & 15, q = lane >> 4;

    unsigned c[4][4][2];
#pragma unroll
    for (int mi = 0; mi < 4; mi++)
#pragma unroll
        for (int ni = 0; ni < 4; ni++) { c[mi][ni][0] = 0u; c[mi][ni][1] = 0u; }

    // strength-reduced loader bases
    const int lrow = tid >> 3, lcol = tid & 7;
    const uint32_t smA = sb + swz(lrow * 128 + lcol * 16);
    const __half* gA0 = g_A + (size_t)by * 128 * DD + lrow * DD + lcol * 8;
    const __half* gB0 = g_B + (size_t)bx * 128 * DD + lrow * DD + lcol * 8;

    // hoisted swizzled ldmatrix offsets; ks folds in via XOR
    const uint32_t qx = (q * 16) ^ ((r16 & 7) << 4);
    uint32_t aoff[4], boff[2];
#pragma unroll
    for (int mi = 0; mi < 4; mi++) aoff[mi] = (wm * 64 + mi * 16 + r16) * 128 + qx;
#pragma unroll
    for (int nh = 0; nh < 2; nh++) boff[nh] = 16384 + (wn * 32 + nh * 16 + r16) * 128 + qx;

    // prologue: stage 0
#pragma unroll
    for (int h = 0; h < 4; h++) {
        cp16(smA + h * 4096,         gA0 + h * 32 * DD);
        cp16(smA + 16384 + h * 4096, gB0 + h * 32 * DD);
    }
    asm volatile("cp.async.commit_group;\n" ::: "memory");

    for (int kt = 0; kt < NKT; kt++) {
        asm volatile("cp.async.wait_group 0;\n" ::: "memory");
        __syncthreads();
        if (kt + 1 < NKT) {
            const __half* ga = gA0 + (kt + 1) * BK;
            const __half* gb = gB0 + (kt + 1) * BK;
            const uint32_t sa = smA + ((kt + 1) & 1) * STAGE_BYTES;
#pragma unroll
            for (int h = 0; h < 4; h++) {
                cp16(sa + h * 4096,         ga + h * 32 * DD);
                cp16(sa + 16384 + h * 4096, gb + h * 32 * DD);
            }
        }
        asm volatile("cp.async.commit_group;\n" ::: "memory");

        const uint32_t base = sb + (kt & 1) * STAGE_BYTES;
#pragma unroll
        for (int ks = 0; ks < 4; ks++) {
            const uint32_t kx = ks << 5;
            unsigned a[4][4];
#pragma unroll
            for (int mi = 0; mi < 4; mi++)
                ldm4(a[mi][0], a[mi][1], a[mi][2], a[mi][3], (base + aoff[mi]) ^ kx);
            unsigned b[4][2];
#pragma unroll
            for (int nh = 0; nh < 2; nh++) {
                unsigned t0, t1, t2, t3;
                ldm4(t0, t1, t2, t3, (base + boff[nh]) ^ kx);
                b[2 * nh][0] = t0;     b[2 * nh][1] = t2;
                b[2 * nh + 1][0] = t1; b[2 * nh + 1][1] = t3;
            }
#pragma unroll
            for (int mi = 0; mi < 4; mi++)
#pragma unroll
                for (int ni = 0; ni < 4; ni++)
                    mma_h(c[mi][ni], a[mi], b[ni]);
        }
    }

    // ---- fused loss epilogue ----
    float acc = 0.f;
#pragma unroll
    for (int mi = 0; mi < 4; mi++) {
        const int i0 = by * 128 + wm * 64 + mi * 16 + (lane >> 2);
        const float pa0 = g_pa[i0], pa1 = g_pa[i0 + 8];
#pragma unroll
        for (int ni = 0; ni < 4; ni++) {
            const int j0 = bx * 128 + wn * 32 + ni * 8 + (lane & 3) * 2;
            const float pb0 = g_pb[j0], pb1 = g_pb[j0 + 1];
            const int2 l0 = *reinterpret_cast<const int2*>(gt + (size_t)i0 * NN + j0);
            const int2 l1 = *reinterpret_cast<const int2*>(gt + (size_t)(i0 + 8) * NN + j0);
            const float2 f0 = __half22float2(*reinterpret_cast<const __half2*>(&c[mi][ni][0]));
            const float2 f1 = __half22float2(*reinterpret_cast<const __half2*>(&c[mi][ni][1]));
            {
                float d2 = fmaxf(fmaf(f0.x, -2.0f, pa0 + pb0), 0.0f);
                if (l0.x) { if (d2 < 4.0f) { float h = 2.0f - sqrtf(d2); acc += h * h; } }
                else acc += d2;
            }
            {
                float d2 = fmaxf(fmaf(f0.y, -2.0f, pa0 + pb1), 0.0f);
                if (l0.y) { if (d2 < 4.0f) { float h = 2.0f - sqrtf(d2); acc += h * h; } }
                else acc += d2;
            }
            {
                float d2 = fmaxf(fmaf(f1.x, -2.0f, pa1 + pb0), 0.0f);
                if (l1.x) { if (d2 < 4.0f) { float h = 2.0f - sqrtf(d2); acc += h * h; } }
                else acc += d2;
            }
            {
                float d2 = fmaxf(fmaf(f1.y, -2.0f, pa1 + pb1), 0.0f);
                if (l1.y) { if (d2 < 4.0f) { float h = 2.0f - sqrtf(d2); acc += h * h; } }
                else acc += d2;
            }
        }
    }

#pragma unroll
    for (int o = 16; o; o >>= 1) acc += __shfl_xor_sync(0xffffffffu, acc, o);
    __shared__ float red[8];
    __shared__ unsigned s_last;
    if (lane == 0) red[warp] = acc;
    __syncthreads();
    if (tid == 0) {
        float s = 0.f;
#pragma unroll
        for (int i = 0; i < 8; i++) s += red[i];
        g_part[by * 32 + bx] = s;
        __threadfence();
        s_last = (atomicAdd(&g_cnt, 1u) == 1023u);
    }
    __syncthreads();

    if (s_last) {
        __threadfence();
        float s = g_part[tid] + g_part[tid + 256] + g_part[tid + 512] + g_part[tid + 768];
#pragma unroll
        for (int o = 16; o; o >>= 1) s += __shfl_xor_sync(0xffffffffu, s, o);
        if (lane == 0) red[warp] = s;
        __syncthreads();
        if (tid == 0) {
            float tot = 0.f;
#pragma unroll
            for (int i = 0; i < 8; i++) tot += red[i];
            out[0] = tot * (1.0f / 16777216.0f);
        }
    }
}

extern "C" void kernel_launch(void* const* d_in, const int* in_sizes, int n_in,
                              void* d_out, int out_size) {
    const float* img = (const float*)d_in[0];
    const float* txt = (const float*)d_in[1];
    const int* gt = (const int*)d_in[2];
    (void)in_sizes; (void)n_in; (void)out_size;

    cudaFuncSetAttribute(gemm_loss_kernel, cudaFuncAttributeMaxDynamicSharedMemorySize, DYN_BYTES);

    prep_kernel<<<1024, 256>>>(img, txt);
    dim3 grid(32, 32);
    gemm_loss_kernel<<<grid, 256, DYN_BYTES>>>(gt, (float*)d_out);
}